// round 15
// baseline (speedup 1.0000x reference)
#include <cuda_runtime.h>
#include <cuda_bf16.h>
#include <math.h>
#include <stdint.h>

#define D_MODEL 512
#define HEADS   8
#define HD      64
#define SEQ     2048
#define BATCH   4
#define MTOT    (BATCH*SEQ)   /* 8192 */
#define KDIM    512
#define KP      256           /* K in bf16x2 uints */
#define BHX     (BATCH*HEADS)
#define WWU     (D_MODEL*KP)  /* uints per 512x512 weight */

// ---------------- scratch (packed bf16 hi/lo everywhere) ---------------------
__device__ __align__(16) uint32_t g_xh[MTOT*KP],    g_xl[MTOT*KP];
__device__ __align__(16) uint32_t g_wh[7*WWU],      g_wl[7*WWU];   // Wq,Wk,Wv,ipw0..2,ow
__device__ __align__(16) uint32_t g_qh[3*MTOT*KP],  g_ql[3*MTOT*KP];  // rotated q,k,v
__device__ __align__(16) uint32_t g_hh[3*MTOT*KP],  g_hl[3*MTOT*KP];  // heads [BH][S][HD/2]
__device__ __align__(16) uint32_t g_ah[MTOT*KP],    g_al[MTOT*KP];    // attn out packed
__device__ float g_tab[SEQ*D_MODEL];                                   // cos/sin

// ---------------- helpers ------------------------------------------------------
__device__ __forceinline__ uint32_t packbf2(float lo, float hi){
    uint32_t r;
    asm("cvt.rn.bf16x2.f32 %0, %1, %2;" : "=r"(r) : "f"(hi), "f"(lo));
    return r;
}
__device__ __forceinline__ void split2(float x, float y, uint32_t& h, uint32_t& l){
    h = packbf2(x, y);
    float hx = __uint_as_float(h << 16);
    float hy = __uint_as_float(h & 0xffff0000u);
    l = packbf2(x - hx, y - hy);
}
__device__ __forceinline__ void ldsm_x4(uint32_t* r, uint32_t addr){
    asm volatile("ldmatrix.sync.aligned.m8n8.x4.shared.b16 {%0,%1,%2,%3}, [%4];"
        : "=r"(r[0]),"=r"(r[1]),"=r"(r[2]),"=r"(r[3]) : "r"(addr));
}
__device__ __forceinline__ void ldsm_x4t(uint32_t* r, uint32_t addr){
    asm volatile("ldmatrix.sync.aligned.m8n8.x4.trans.shared.b16 {%0,%1,%2,%3}, [%4];"
        : "=r"(r[0]),"=r"(r[1]),"=r"(r[2]),"=r"(r[3]) : "r"(addr));
}
__device__ __forceinline__ void mma_bf16(float* c, const uint32_t* a, uint32_t b0, uint32_t b1){
    asm volatile("mma.sync.aligned.m16n8k16.row.col.f32.bf16.bf16.f32 "
        "{%0,%1,%2,%3},{%4,%5,%6,%7},{%8,%9},{%0,%1,%2,%3};"
        : "+f"(c[0]),"+f"(c[1]),"+f"(c[2]),"+f"(c[3])
        : "r"(a[0]),"r"(a[1]),"r"(a[2]),"r"(a[3]),"r"(b0),"r"(b1));
}
__device__ __forceinline__ void cpasync16(uint32_t saddr, const void* g){
    asm volatile("cp.async.cg.shared.global [%0], [%1], 16;" :: "r"(saddr), "l"(g));
}

// ---------------- split fp32 -> packed bf16 hi/lo -----------------------------
__global__ void split_kernel(const float2* __restrict__ src,
                             uint32_t* __restrict__ h, uint32_t* __restrict__ l, int n2){
    int i = blockIdx.x*256 + threadIdx.x;
    if (i < n2){
        float2 v = src[i];
        uint32_t hh, ll;
        split2(v.x, v.y, hh, ll);
        h[i] = hh; l[i] = ll;
    }
}

// batched weight split: jobs = Wq, Wk, Wv, ipw(3x), ow -> g_wh/g_wl layout
__global__ void split_w_kernel(const float2* __restrict__ w0, const float2* __restrict__ w1,
                               const float2* __restrict__ w2, const float2* __restrict__ w3,
                               const float2* __restrict__ w4,
                               uint32_t* __restrict__ h, uint32_t* __restrict__ l){
    int j = blockIdx.y;
    const float2* src;
    uint32_t off; int n2;
    if      (j == 0){ src = w0; off = 0;     n2 = WWU;   }
    else if (j == 1){ src = w1; off = WWU;   n2 = WWU;   }
    else if (j == 2){ src = w2; off = 2*WWU; n2 = WWU;   }
    else if (j == 3){ src = w3; off = 3*WWU; n2 = 3*WWU; }
    else            { src = w4; off = 6*WWU; n2 = WWU;   }
    for (int i = blockIdx.x*256 + threadIdx.x; i < n2; i += gridDim.x*256){
        float2 v = src[i];
        uint32_t hh, ll;
        split2(v.x, v.y, hh, ll);
        h[off + i] = hh; l[off + i] = ll;
    }
}

// ---------------- RoPE table ---------------------------------------------------
__global__ void rope_table_kernel(const float* __restrict__ R, float* __restrict__ tab){
    int i = threadIdx.x;
    int m = blockIdx.x;
    const float* Rm = R + (size_t)m * D_MODEL * D_MODEL;
    float c = Rm[(size_t)(2*i)   * D_MODEL + 2*i];
    float s = Rm[(size_t)(2*i+1) * D_MODEL + 2*i];
    ((float2*)tab)[m*(D_MODEL/2) + i] = make_float2(c, s);
}

// ---------------- bf16x3 GEMM on packed operands: C = A @ B^T -----------------
// Tile 128(M) x 64(N), BK=16, 4-buffer cp.async ring (3-stage lookahead),
// 8 warps (4m x 2n), warp tile 32x32 -> 32-float acc -> 3 CTAs/SM (24 warps).
// Row pad = 12 uints (48 B): 16B-aligned, conflict-free ldmatrix banks.
// MODE 0: +bias fp32 out  MODE 1: +bias head-permute packed  MODE 2: RoPE packed
#define RBA   1536                      /* A region: 128 rows x 12 uints      */
#define RBB   768                       /* B region:  64 rows x 12 uints      */
#define OF_AL (RBA)
#define OF_BH (2*RBA)
#define OF_BL (2*RBA + RBB)
#define BUF4  (2*RBA + 2*RBB)           /* 4608 uints = 18432 B per buffer    */
#define GEMM_SMEM (4*BUF4*4)            /* 73728 B */

template<int MODE>
__global__ void __launch_bounds__(256, 3) gemm_pk(
    const uint32_t* __restrict__ Ah, const uint32_t* __restrict__ Al, long sA,
    const uint32_t* __restrict__ Bh, const uint32_t* __restrict__ Bl, long sB,
    const float* __restrict__ bias, long sBias,
    float* __restrict__ Cf, uint32_t* __restrict__ Ch, uint32_t* __restrict__ Cl,
    long sC, const float* __restrict__ tab)
{
    extern __shared__ uint32_t smu[];
    int z = blockIdx.z;
    Ah += (size_t)z * sA;  Al += (size_t)z * sA;
    Bh += (size_t)z * sB;  Bl += (size_t)z * sB;
    if (bias) bias += (size_t)z * sBias;

    int tid  = threadIdx.x;
    int lane = tid & 31, wid = tid >> 5;
    int warp_m = wid >> 1, warp_n = wid & 1;
    int m0 = blockIdx.y * 128, n0 = blockIdx.x * 64;

    uint32_t smb = (uint32_t)__cvta_generic_to_shared(smu);

    // loaders: A = all 256 threads (128 rows x 2 chunks); B = threads 0-127
    int arow = tid >> 1, ahf = (tid & 1) * 4;
    const uint32_t* gAh = Ah + (size_t)(m0 + arow)*KP + ahf;
    const uint32_t* gAl = Al + (size_t)(m0 + arow)*KP + ahf;
    uint32_t saA = smb + (arow*12 + ahf)*4;
    const uint32_t* gBh = Bh + (size_t)(n0 + (tid >> 1))*KP + ahf;   // valid for tid<128
    const uint32_t* gBl = Bl + (size_t)(n0 + (tid >> 1))*KP + ahf;
    uint32_t saB = smb + ((tid >> 1)*12 + ahf)*4;
    bool bload = tid < 128;

    const int NS = KDIM / 16;   // 32 stages
    auto issue = [&](int s){
        if (s < NS){
            uint32_t bo = (uint32_t)((s & 3) * BUF4 * 4);
            int go = s * 8;
            cpasync16(bo + saA,             gAh + go);
            cpasync16(bo + saA + OF_AL*4,   gAl + go);
            if (bload){
                cpasync16(bo + saB + OF_BH*4, gBh + go);
                cpasync16(bo + saB + OF_BL*4, gBl + go);
            }
        }
        asm volatile("cp.async.commit_group;");   // empty group past the end
    };

    float acc[2][4][4] = {};
    uint32_t a_base = (uint32_t)((warp_m*32 + (lane & 15)) * 48 + (lane >> 4) * 16);
    uint32_t b_base = (uint32_t)((warp_n*32 + (lane & 15)) * 48 + (lane >> 4) * 16);

    issue(0); issue(1); issue(2);
    for (int s = 0; s < NS; s++){
        asm volatile("cp.async.wait_group 2;");
        __syncthreads();
        issue(s + 3);
        uint32_t bb = smb + (uint32_t)((s & 3) * BUF4 * 4);

        uint32_t AHf[2][4], ALf[2][4];
        #pragma unroll
        for (int mi = 0; mi < 2; mi++){
            uint32_t aa = bb + a_base + mi*16*48;
            ldsm_x4(AHf[mi], aa);
            ldsm_x4(ALf[mi], aa + OF_AL*4);
        }
        #pragma unroll
        for (int nb = 0; nb < 2; nb++){
            uint32_t BHf[4], BLf[4];
            uint32_t ba = bb + OF_BH*4 + b_base + nb*16*48;
            ldsm_x4(BHf, ba);
            ldsm_x4(BLf, ba + (OF_BL - OF_BH)*4);
            #pragma unroll
            for (int mi = 0; mi < 2; mi++){
                mma_bf16(acc[mi][2*nb],   AHf[mi], BHf[0], BHf[2]);
                mma_bf16(acc[mi][2*nb+1], AHf[mi], BHf[1], BHf[3]);
                mma_bf16(acc[mi][2*nb],   AHf[mi], BLf[0], BLf[2]);
                mma_bf16(acc[mi][2*nb+1], AHf[mi], BLf[1], BLf[3]);
                mma_bf16(acc[mi][2*nb],   ALf[mi], BHf[0], BHf[2]);
                mma_bf16(acc[mi][2*nb+1], ALf[mi], BHf[1], BHf[3]);
            }
        }
        // no trailing barrier: next stage's post-wait barrier orders these
        // smem reads before issue(s+4) overwrites this buffer.
    }

    // ---------------- epilogue ----------------
    const float2* tab2 = (const float2*)tab;
    #pragma unroll
    for (int mi = 0; mi < 2; mi++){
        #pragma unroll
        for (int ni = 0; ni < 4; ni++){
            int m = m0 + warp_m*32 + mi*16 + (lane >> 2);
            int n = n0 + warp_n*32 + ni*8 + (lane & 3)*2;
            float v0 = acc[mi][ni][0], v1 = acc[mi][ni][1];   // row m
            float v2 = acc[mi][ni][2], v3 = acc[mi][ni][3];   // row m+8
            if (MODE == 2){
                float2 cs0 = tab2[(m     & (SEQ-1)) * (D_MODEL/2) + (n >> 1)];
                float2 cs1 = tab2[((m+8) & (SEQ-1)) * (D_MODEL/2) + (n >> 1)];
                float o0 =  v0*cs0.x + v1*cs0.y;
                float o1 = -v0*cs0.y + v1*cs0.x;
                float o2 =  v2*cs1.x + v3*cs1.y;
                float o3 = -v2*cs1.y + v3*cs1.x;
                v0=o0; v1=o1; v2=o2; v3=o3;
            } else {
                float b0 = bias[n], b1 = bias[n+1];
                v0 += b0; v1 += b1; v2 += b0; v3 += b1;
            }
            if (MODE == 0){
                float* C = Cf + (size_t)z * sC;
                *(float2*)&C[(size_t)m*D_MODEL + n]     = make_float2(v0, v1);
                *(float2*)&C[(size_t)(m+8)*D_MODEL + n] = make_float2(v2, v3);
            } else {
                uint32_t h0,l0,h1,l1;
                split2(v0, v1, h0, l0);
                split2(v2, v3, h1, l1);
                size_t zo = (size_t)z * sC;
                if (MODE == 1){
                    int b = m >> 11, sq = m & (SEQ-1);
                    int hh = n >> 6,  c = n & (HD-1);
                    size_t i0 = (((size_t)(b*HEADS + hh))*SEQ + sq)*(HD/2) + (c>>1);
                    Ch[zo + i0]            = h0;  Cl[zo + i0]            = l0;
                    Ch[zo + i0 + 8*(HD/2)] = h1;  Cl[zo + i0 + 8*(HD/2)] = l1;
                } else { // MODE 2
                    size_t i0 = (size_t)m*KP + (n>>1);
                    Ch[zo + i0]        = h0;  Cl[zo + i0]        = l0;
                    Ch[zo + i0 + 8*KP] = h1;  Cl[zo + i0 + 8*KP] = l1;
                }
            }
        }
    }
}

// ---------------- Tensor-core flash attention (causal) ------------------------
// Double-buffered cp.async K/V pipeline. Q,K,V packed bf16 hi/lo [BH][S][HD/2];
// output packed [B][S][D/2]. Warps 0-3 skip the fully-masked last k-tile.
#define FROW 36
#define FBUF (256*FROW)                 /* uints per K/V buffer (KH,KL,VH,VL)  */
#define FKL_OFF (64*FROW*4)             /* byte offsets inside a buffer        */
#define FVH_OFF (128*FROW*4)
#define FVL_OFF (192*FROW*4)
#define FLASH_SMEM (2*FBUF*4)           /* 73728 B */

__global__ void __launch_bounds__(256) flash_tc(
    const uint32_t* __restrict__ Qh, const uint32_t* __restrict__ Ql,
    const uint32_t* __restrict__ Kh, const uint32_t* __restrict__ Kl,
    const uint32_t* __restrict__ Vh, const uint32_t* __restrict__ Vl,
    uint32_t* __restrict__ Oh, uint32_t* __restrict__ Ol)
{
    extern __shared__ uint32_t sm[];
    int tid = threadIdx.x, lane = tid & 31, wid = tid >> 5;
    int qblk = gridDim.x - 1 - blockIdx.x;          // heavy blocks first
    int q0 = qblk * 128;
    int bh = blockIdx.y;
    size_t base = (size_t)bh * SEQ * (HD/2);

    uint32_t smb = (uint32_t)__cvta_generic_to_shared(sm);

    // ---- stage Q into buffer0 area, extract persistent fragments ----
    {
        int r = tid >> 1, hs = (tid & 1) * 16;
        const uint4* gh = (const uint4*)(Qh + base + (size_t)(q0 + r)*(HD/2) + hs);
        const uint4* gl = (const uint4*)(Ql + base + (size_t)(q0 + r)*(HD/2) + hs);
        uint4* dh = (uint4*)(sm + r*FROW + hs);
        uint4* dl = (uint4*)(sm + 128*FROW + r*FROW + hs);
        dh[0]=gh[0]; dh[1]=gh[1]; dh[2]=gh[2]; dh[3]=gh[3];
        dl[0]=gl[0]; dl[1]=gl[1]; dl[2]=gl[2]; dl[3]=gl[3];
    }
    __syncthreads();

    uint32_t qh[4][4], ql[4][4];
    {
        uint32_t qa = smb + (uint32_t)(((wid*16 + (lane & 15))*FROW)*4 + (lane >> 4)*16);
        #pragma unroll
        for (int t = 0; t < 4; t++){
            ldsm_x4(qh[t], qa + t*32);
            ldsm_x4(ql[t], qa + 128*FROW*4 + t*32);
        }
    }
    __syncthreads();   // Q staging fully read; buffers free for cp.async

    // K/V loader assignment
    int lr = tid >> 2;
    int lc = (tid & 3) * 8;
    uint32_t so = (uint32_t)((lr*FROW + lc)*4);

    auto kv_issue = [&](int t){
        uint32_t bb = smb + (uint32_t)((t & 1) * FBUF * 4);
        size_t gi = base + (size_t)(t*64 + lr)*(HD/2) + lc;
        cpasync16(bb + so,                 Kh + gi);
        cpasync16(bb + so + 16,            Kh + gi + 4);
        cpasync16(bb + FKL_OFF + so,       Kl + gi);
        cpasync16(bb + FKL_OFF + so + 16,  Kl + gi + 4);
        cpasync16(bb + FVH_OFF + so,       Vh + gi);
        cpasync16(bb + FVH_OFF + so + 16,  Vh + gi + 4);
        cpasync16(bb + FVL_OFF + so,       Vl + gi);
        cpasync16(bb + FVL_OFF + so + 16,  Vl + gi + 4);
        asm volatile("cp.async.commit_group;");
    };

    float o[8][4] = {};
    float mr0 = -INFINITY, mr1 = -INFINITY, l0 = 0.f, l1 = 0.f;
    const float scale = 0.125f;
    int r0g = q0 + wid*16 + (lane >> 2);
    int r1g = r0g + 8;

    int ktiles = 2*qblk + 2;
    kv_issue(0);
    for (int t = 0; t < ktiles; t++){
        int k0 = t * 64;
        if (t + 1 < ktiles){
            kv_issue(t + 1);
            asm volatile("cp.async.wait_group 1;");
        } else {
            asm volatile("cp.async.wait_group 0;");
        }
        __syncthreads();
        uint32_t bufo = (uint32_t)((t & 1) * FBUF * 4);

        // Last k-tile is entirely above the diagonal for warps 0-3 — skip.
        if (!(t == ktiles - 1 && wid < 4)){

        // ---- S = Q K^T (bf16x3) ----
        float s[8][4] = {};
        #pragma unroll
        for (int t4 = 0; t4 < 4; t4++){
            #pragma unroll
            for (int nb = 0; nb < 4; nb++){
                uint32_t ba = smb + bufo
                            + (uint32_t)(((nb*16 + (lane & 15))*FROW)*4 + (lane >> 4)*16 + t4*32);
                uint32_t kh4[4], kl4[4];
                ldsm_x4(kh4, ba);
                ldsm_x4(kl4, ba + FKL_OFF);
                mma_bf16(s[2*nb],   qh[t4], kh4[0], kh4[2]);
                mma_bf16(s[2*nb+1], qh[t4], kh4[1], kh4[3]);
                mma_bf16(s[2*nb],   qh[t4], kl4[0], kl4[2]);
                mma_bf16(s[2*nb+1], qh[t4], kl4[1], kl4[3]);
                mma_bf16(s[2*nb],   ql[t4], kh4[0], kh4[2]);
                mma_bf16(s[2*nb+1], ql[t4], kh4[1], kh4[3]);
            }
        }

        // ---- scale + causal mask ----
        bool need_mask = (t == ktiles - 1) || (t == ktiles - 2 && wid < 4);
        #pragma unroll
        for (int f = 0; f < 8; f++){
            int colb = k0 + (f>>1)*16 + (f&1)*8 + (lane & 3)*2;
            #pragma unroll
            for (int c = 0; c < 4; c++){
                float v = s[f][c] * scale;
                if (need_mask){
                    int kg = colb + (c & 1);
                    int qg = (c < 2) ? r0g : r1g;
                    if (kg > qg) v = -1e30f;
                }
                s[f][c] = v;
            }
        }

        // ---- online softmax ----
        float mx0 = -INFINITY, mx1 = -INFINITY;
        #pragma unroll
        for (int f = 0; f < 8; f++){
            mx0 = fmaxf(mx0, fmaxf(s[f][0], s[f][1]));
            mx1 = fmaxf(mx1, fmaxf(s[f][2], s[f][3]));
        }
        mx0 = fmaxf(mx0, __shfl_xor_sync(0xffffffffu, mx0, 1));
        mx0 = fmaxf(mx0, __shfl_xor_sync(0xffffffffu, mx0, 2));
        mx1 = fmaxf(mx1, __shfl_xor_sync(0xffffffffu, mx1, 1));
        mx1 = fmaxf(mx1, __shfl_xor_sync(0xffffffffu, mx1, 2));
        float mn0 = fmaxf(mr0, mx0), mn1 = fmaxf(mr1, mx1);
        float a0 = __expf(mr0 - mn0), a1 = __expf(mr1 - mn1);
        mr0 = mn0; mr1 = mn1;
        float ps0 = 0.f, ps1 = 0.f;
        #pragma unroll
        for (int f = 0; f < 8; f++){
            s[f][0] = __expf(s[f][0] - mn0);
            s[f][1] = __expf(s[f][1] - mn0);
            s[f][2] = __expf(s[f][2] - mn1);
            s[f][3] = __expf(s[f][3] - mn1);
            ps0 += s[f][0] + s[f][1];
            ps1 += s[f][2] + s[f][3];
        }
        ps0 += __shfl_xor_sync(0xffffffffu, ps0, 1);
        ps0 += __shfl_xor_sync(0xffffffffu, ps0, 2);
        ps1 += __shfl_xor_sync(0xffffffffu, ps1, 1);
        ps1 += __shfl_xor_sync(0xffffffffu, ps1, 2);
        l0 = l0 * a0 + ps0;
        l1 = l1 * a1 + ps1;
        #pragma unroll
        for (int f = 0; f < 8; f++){
            o[f][0] *= a0; o[f][1] *= a0;
            o[f][2] *= a1; o[f][3] *= a1;
        }

        // ---- P fragments (in-register split) ----
        uint32_t ph[4][4], pl[4][4];
        #pragma unroll
        for (int t4 = 0; t4 < 4; t4++){
            split2(s[2*t4][0],   s[2*t4][1],   ph[t4][0], pl[t4][0]);
            split2(s[2*t4][2],   s[2*t4][3],   ph[t4][1], pl[t4][1]);
            split2(s[2*t4+1][0], s[2*t4+1][1], ph[t4][2], pl[t4][2]);
            split2(s[2*t4+1][2], s[2*t4+1][3], ph[t4][3], pl[t4][3]);
        }

        // ---- O += P V (bf16x3) ----
        #pragma unroll
        for (int t4 = 0; t4 < 4; t4++){
            #pragma unroll
            for (int nb = 0; nb < 4; nb++){
                uint32_t va = smb + bufo
                            + (uint32_t)(((t4*16 + (lane & 15))*FROW)*4 + (lane >> 4)*16 + nb*32);
                uint32_t vh4[4], vl4[4];
                ldsm_x4t(vh4, va + FVH_OFF);
                ldsm_x4t(vl4, va + FVL_OFF);
                mma_bf16(o[2*nb],   ph[t4], vh4[0], vh4[1]);
                mma_bf16(o[2*nb+1], ph[t4], vh4[2], vh4[3]);
                mma_bf16(o[2*nb],   ph[t4], vl4[0], vl4[1]);
                mma_bf16(o[2*nb+1], ph[t4], vl4[2], vl4[3]);
                mma_bf16(o[2*nb],   pl[t4], vh4[0], vh4[1]);
                mma_bf16(o[2*nb+1], pl[t4], vh4[2], vh4[3]);
            }
        }

        }  // end warp-skip

        __syncthreads();   // reads of this buffer done before t+2 overwrites it
    }

    // epilogue: normalize, split, write packed attn [B,S,D/2]
    int b = bh >> 3, h = bh & 7;
    float inv0 = 1.0f / l0, inv1 = 1.0f / l1;
    #pragma unroll
    for (int f = 0; f < 8; f++){
        int col = h*HD + (f>>1)*16 + (f&1)*8 + (lane & 3)*2;
        uint32_t h0,l0u,h1,l1u;
        split2(o[f][0]*inv0, o[f][1]*inv0, h0, l0u);
        split2(o[f][2]*inv1, o[f][3]*inv1, h1, l1u);
        size_t i0 = (size_t)(b*SEQ + r0g)*KP + (col>>1);
        size_t i1 = (size_t)(b*SEQ + r1g)*KP + (col>>1);
        Oh[i0] = h0;  Ol[i0] = l0u;
        Oh[i1] = h1;  Ol[i1] = l1u;
    }
}

// ---------------- launch ------------------------------------------------------
extern "C" void kernel_launch(void* const* d_in, const int* in_sizes, int n_in,
                              void* d_out, int out_size) {
    const float* x   = (const float*)d_in[0];
    const float* Wq  = (const float*)d_in[1];
    const float* Wk  = (const float*)d_in[2];
    const float* Wv  = (const float*)d_in[3];
    const float* R   = (const float*)d_in[4];
    const float* ipw = (const float*)d_in[5];
    const float* ipb = (const float*)d_in[6];
    const float* ow  = (const float*)d_in[7];
    const float* ob  = (const float*)d_in[8];
    float* out = (float*)d_out;

    uint32_t *xh,*xl,*wh,*wl,*qh,*ql,*hh,*hl,*ah,*al;
    float* tab;
    cudaGetSymbolAddress((void**)&xh, g_xh);  cudaGetSymbolAddress((void**)&xl, g_xl);
    cudaGetSymbolAddress((void**)&wh, g_wh);  cudaGetSymbolAddress((void**)&wl, g_wl);
    cudaGetSymbolAddress((void**)&qh, g_qh);  cudaGetSymbolAddress((void**)&ql, g_ql);
    cudaGetSymbolAddress((void**)&hh, g_hh);  cudaGetSymbolAddress((void**)&hl, g_hl);
    cudaGetSymbolAddress((void**)&ah, g_ah);  cudaGetSymbolAddress((void**)&al, g_al);
    cudaGetSymbolAddress((void**)&tab, g_tab);

    static int inited = 0;
    if (!inited) {
        cudaFuncSetAttribute(gemm_pk<0>, cudaFuncAttributeMaxDynamicSharedMemorySize, GEMM_SMEM);
        cudaFuncSetAttribute(gemm_pk<1>, cudaFuncAttributeMaxDynamicSharedMemorySize, GEMM_SMEM);
        cudaFuncSetAttribute(gemm_pk<2>, cudaFuncAttributeMaxDynamicSharedMemorySize, GEMM_SMEM);
        cudaFuncSetAttribute(flash_tc,   cudaFuncAttributeMaxDynamicSharedMemorySize, FLASH_SMEM);
        inited = 1;
    }

    const long MKP = (long)MTOT * KP;

    // 0) cos/sin table + splits (x separate; weights batched into one launch)
    rope_table_kernel<<<SEQ, 256>>>(R, tab);
    split_kernel<<<(MTOT*KP)/256, 256>>>((const float2*)x, xh, xl, MTOT*KP);
    split_w_kernel<<<dim3(512, 5), 256>>>((const float2*)Wq, (const float2*)Wk,
                                          (const float2*)Wv, (const float2*)ipw,
                                          (const float2*)ow, wh, wl);

    // 1) q,k,v = x @ W^T with fused RoPE, packed out (z-batched over 3 weights)
    dim3 gq(D_MODEL/64, MTOT/128, 3);
    gemm_pk<2><<<gq, 256, GEMM_SMEM>>>(xh, xl, 0, wh, wl, WWU,
                                       nullptr, 0, nullptr, qh, ql, MKP, tab);

    // 2) in_proj: bias + head-permute + packed out (z-batched)
    dim3 gi(D_MODEL/64, MTOT/128, 3);
    gemm_pk<1><<<gi, 256, GEMM_SMEM>>>(qh, ql, MKP, wh + 3*WWU, wl + 3*WWU, WWU,
                                       ipb, D_MODEL, nullptr, hh, hl, MKP, nullptr);

    // 3) causal flash attention -> packed attn
    flash_tc<<<dim3(SEQ/128, BHX), 256, FLASH_SMEM>>>(
        hh, hl, hh + MKP, hl + MKP, hh + 2*MKP, hl + 2*MKP, ah, al);

    // 4) output projection (fp32 out)
    dim3 go(D_MODEL/64, MTOT/128, 1);
    gemm_pk<0><<<go, 256, GEMM_SMEM>>>(ah, al, 0, wh + 6*WWU, wl + 6*WWU, 0,
                                       ob, 0, out, nullptr, nullptr, 0, nullptr);
}

// round 16
// speedup vs baseline: 1.3999x; 1.3999x over previous
#include <cuda_runtime.h>
#include <cuda_fp16.h>
#include <math.h>
#include <stdint.h>

#define D_MODEL 512
#define HEADS   8
#define HD      64
#define SEQ     2048
#define BATCH   4
#define MTOT    (BATCH*SEQ)   /* 8192 */
#define KDIM    512
#define KP      256           /* K in f16x2 uints */
#define BHX     (BATCH*HEADS)
#define WWU     (D_MODEL*KP)  /* uints per 512x512 weight */

// ---------------- scratch (packed fp16 hi/lo) ---------------------------------
__device__ __align__(16) uint32_t g_xh[MTOT*KP],    g_xl[MTOT*KP];
__device__ __align__(16) uint32_t g_wh[7*WWU];                     // weights: hi only
__device__ __align__(16) uint32_t g_qh[3*MTOT*KP],  g_ql[3*MTOT*KP];  // rotated q,k,v
__device__ __align__(16) uint32_t g_hh[3*MTOT*KP],  g_hl[3*MTOT*KP];  // heads [BH][S][HD/2]
__device__ __align__(16) uint32_t g_ah[MTOT*KP],    g_al[MTOT*KP];    // attn out packed
__device__ float g_tab[SEQ*D_MODEL];                                   // cos/sin

// ---------------- helpers ------------------------------------------------------
__device__ __forceinline__ void split2(float x, float y, uint32_t& h, uint32_t& l){
    __half2 hh = __floats2half2_rn(x, y);
    h = *(uint32_t*)&hh;
    float hx = __low2float(hh), hy = __high2float(hh);
    __half2 ll = __floats2half2_rn(x - hx, y - hy);
    l = *(uint32_t*)&ll;
}
__device__ __forceinline__ uint32_t round_h2(float x, float y){
    __half2 hh = __floats2half2_rn(x, y);
    return *(uint32_t*)&hh;
}
__device__ __forceinline__ void ldsm_x4(uint32_t* r, uint32_t addr){
    asm volatile("ldmatrix.sync.aligned.m8n8.x4.shared.b16 {%0,%1,%2,%3}, [%4];"
        : "=r"(r[0]),"=r"(r[1]),"=r"(r[2]),"=r"(r[3]) : "r"(addr));
}
__device__ __forceinline__ void ldsm_x4t(uint32_t* r, uint32_t addr){
    asm volatile("ldmatrix.sync.aligned.m8n8.x4.trans.shared.b16 {%0,%1,%2,%3}, [%4];"
        : "=r"(r[0]),"=r"(r[1]),"=r"(r[2]),"=r"(r[3]) : "r"(addr));
}
__device__ __forceinline__ void mma_h(float* c, const uint32_t* a, uint32_t b0, uint32_t b1){
    asm volatile("mma.sync.aligned.m16n8k16.row.col.f32.f16.f16.f32 "
        "{%0,%1,%2,%3},{%4,%5,%6,%7},{%8,%9},{%0,%1,%2,%3};"
        : "+f"(c[0]),"+f"(c[1]),"+f"(c[2]),"+f"(c[3])
        : "r"(a[0]),"r"(a[1]),"r"(a[2]),"r"(a[3]),"r"(b0),"r"(b1));
}
__device__ __forceinline__ void cpasync16(uint32_t saddr, const void* g){
    asm volatile("cp.async.cg.shared.global [%0], [%1], 16;" :: "r"(saddr), "l"(g));
}

// ---------------- split fp32 -> packed fp16 hi/lo ------------------------------
__global__ void split_kernel(const float2* __restrict__ src,
                             uint32_t* __restrict__ h, uint32_t* __restrict__ l, int n2){
    int i = blockIdx.x*256 + threadIdx.x;
    if (i < n2){
        float2 v = src[i];
        uint32_t hh, ll;
        split2(v.x, v.y, hh, ll);
        h[i] = hh; l[i] = ll;
    }
}

// batched weight round (hi only): Wq, Wk, Wv, ipw(3x), ow -> g_wh layout
__global__ void split_w_kernel(const float2* __restrict__ w0, const float2* __restrict__ w1,
                               const float2* __restrict__ w2, const float2* __restrict__ w3,
                               const float2* __restrict__ w4,
                               uint32_t* __restrict__ h){
    int j = blockIdx.y;
    const float2* src;
    uint32_t off; int n2;
    if      (j == 0){ src = w0; off = 0;     n2 = WWU;   }
    else if (j == 1){ src = w1; off = WWU;   n2 = WWU;   }
    else if (j == 2){ src = w2; off = 2*WWU; n2 = WWU;   }
    else if (j == 3){ src = w3; off = 3*WWU; n2 = 3*WWU; }
    else            { src = w4; off = 6*WWU; n2 = WWU;   }
    for (int i = blockIdx.x*256 + threadIdx.x; i < n2; i += gridDim.x*256){
        float2 v = src[i];
        h[off + i] = round_h2(v.x, v.y);
    }
}

// ---------------- RoPE table ---------------------------------------------------
__global__ void rope_table_kernel(const float* __restrict__ R, float* __restrict__ tab){
    int i = threadIdx.x;
    int m = blockIdx.x;
    const float* Rm = R + (size_t)m * D_MODEL * D_MODEL;
    float c = Rm[(size_t)(2*i)   * D_MODEL + 2*i];
    float s = Rm[(size_t)(2*i+1) * D_MODEL + 2*i];
    ((float2*)tab)[m*(D_MODEL/2) + i] = make_float2(c, s);
}

// ---------------- fp16x2 GEMM: C = (Ah+Al) @ Bh^T ------------------------------
// Tile 128x128, BK=16, 4-buffer cp.async ring, 8 warps (4m x 2n).
// Regions per buffer: AH, AL (128 rows), BH (128 rows); row pad 12 uints (48B).
// MODE 0: +bias fp32 out  MODE 1: +bias head-permute packed  MODE 2: RoPE packed
#define RB    1536                      /* region stride, uints (128 x 12)    */
#define OF_AL RB
#define OF_BH (2*RB)
#define BUF4  (3*RB)                    /* 4608 uints = 18432 B per buffer    */
#define GEMM_SMEM (4*BUF4*4)            /* 73728 B */

template<int MODE>
__global__ void __launch_bounds__(256, 2) gemm_pk(
    const uint32_t* __restrict__ Ah, const uint32_t* __restrict__ Al, long sA,
    const uint32_t* __restrict__ Bh, long sB,
    const float* __restrict__ bias, long sBias,
    float* __restrict__ Cf, uint32_t* __restrict__ Ch, uint32_t* __restrict__ Cl,
    long sC, const float* __restrict__ tab)
{
    extern __shared__ uint32_t smu[];
    int z = blockIdx.z;
    Ah += (size_t)z * sA;  Al += (size_t)z * sA;
    Bh += (size_t)z * sB;
    if (bias) bias += (size_t)z * sBias;

    int tid  = threadIdx.x;
    int lane = tid & 31, wid = tid >> 5;
    int warp_m = wid >> 1, warp_n = wid & 1;
    int m0 = blockIdx.y * 128, n0 = blockIdx.x * 128;

    uint32_t smb = (uint32_t)__cvta_generic_to_shared(smu);

    int row = tid >> 1, hf = (tid & 1) * 4;
    const uint32_t* gAh = Ah + (size_t)(m0 + row)*KP + hf;
    const uint32_t* gAl = Al + (size_t)(m0 + row)*KP + hf;
    const uint32_t* gBh = Bh + (size_t)(n0 + row)*KP + hf;
    uint32_t sa = smb + (row*12 + hf)*4;

    const int NS = KDIM / 16;   // 32 stages
    auto issue = [&](int s){
        if (s < NS){
            uint32_t bo = (uint32_t)((s & 3) * BUF4 * 4);
            int go = s * 8;
            cpasync16(bo + sa,            gAh + go);
            cpasync16(bo + sa + OF_AL*4,  gAl + go);
            cpasync16(bo + sa + OF_BH*4,  gBh + go);
        }
        asm volatile("cp.async.commit_group;");
    };

    float acc[2][8][4] = {};
    uint32_t a_base = (uint32_t)((warp_m*32 + (lane & 15)) * 48 + (lane >> 4) * 16);
    uint32_t b_base = (uint32_t)((warp_n*64 + (lane & 15)) * 48 + (lane >> 4) * 16);

    issue(0); issue(1); issue(2);
    for (int s = 0; s < NS; s++){
        asm volatile("cp.async.wait_group 2;");
        __syncthreads();
        issue(s + 3);
        uint32_t bb = smb + (uint32_t)((s & 3) * BUF4 * 4);

        uint32_t AHf[2][4], ALf[2][4];
        #pragma unroll
        for (int mi = 0; mi < 2; mi++){
            uint32_t aa = bb + a_base + mi*16*48;
            ldsm_x4(AHf[mi], aa);
            ldsm_x4(ALf[mi], aa + OF_AL*4);
        }
        #pragma unroll
        for (int nb = 0; nb < 4; nb++){
            uint32_t BHf[4];
            ldsm_x4(BHf, bb + OF_BH*4 + b_base + nb*16*48);
            #pragma unroll
            for (int mi = 0; mi < 2; mi++){
                mma_h(acc[mi][2*nb],   AHf[mi], BHf[0], BHf[2]);
                mma_h(acc[mi][2*nb+1], AHf[mi], BHf[1], BHf[3]);
                mma_h(acc[mi][2*nb],   ALf[mi], BHf[0], BHf[2]);
                mma_h(acc[mi][2*nb+1], ALf[mi], BHf[1], BHf[3]);
            }
        }
    }

    // ---------------- epilogue ----------------
    const float2* tab2 = (const float2*)tab;
    #pragma unroll
    for (int mi = 0; mi < 2; mi++){
        #pragma unroll
        for (int ni = 0; ni < 8; ni++){
            int m = m0 + warp_m*32 + mi*16 + (lane >> 2);
            int n = n0 + warp_n*64 + ni*8 + (lane & 3)*2;
            float v0 = acc[mi][ni][0], v1 = acc[mi][ni][1];   // row m
            float v2 = acc[mi][ni][2], v3 = acc[mi][ni][3];   // row m+8
            if (MODE == 2){
                float2 cs0 = tab2[(m     & (SEQ-1)) * (D_MODEL/2) + (n >> 1)];
                float2 cs1 = tab2[((m+8) & (SEQ-1)) * (D_MODEL/2) + (n >> 1)];
                float o0 =  v0*cs0.x + v1*cs0.y;
                float o1 = -v0*cs0.y + v1*cs0.x;
                float o2 =  v2*cs1.x + v3*cs1.y;
                float o3 = -v2*cs1.y + v3*cs1.x;
                v0=o0; v1=o1; v2=o2; v3=o3;
            } else {
                float b0 = bias[n], b1 = bias[n+1];
                v0 += b0; v1 += b1; v2 += b0; v3 += b1;
            }
            if (MODE == 0){
                float* C = Cf + (size_t)z * sC;
                *(float2*)&C[(size_t)m*D_MODEL + n]     = make_float2(v0, v1);
                *(float2*)&C[(size_t)(m+8)*D_MODEL + n] = make_float2(v2, v3);
            } else {
                uint32_t h0,l0,h1,l1;
                split2(v0, v1, h0, l0);
                split2(v2, v3, h1, l1);
                size_t zo = (size_t)z * sC;
                if (MODE == 1){
                    int b = m >> 11, sq = m & (SEQ-1);
                    int hh = n >> 6,  c = n & (HD-1);
                    size_t i0 = (((size_t)(b*HEADS + hh))*SEQ + sq)*(HD/2) + (c>>1);
                    Ch[zo + i0]            = h0;  Cl[zo + i0]            = l0;
                    Ch[zo + i0 + 8*(HD/2)] = h1;  Cl[zo + i0 + 8*(HD/2)] = l1;
                } else { // MODE 2
                    size_t i0 = (size_t)m*KP + (n>>1);
                    Ch[zo + i0]        = h0;  Cl[zo + i0]        = l0;
                    Ch[zo + i0 + 8*KP] = h1;  Cl[zo + i0 + 8*KP] = l1;
                }
            }
        }
    }
}

// ---------------- fp16x2 flash attention (causal) ------------------------------
// Q split (hi+lo) in registers; K,V hi-only in smem (double-buffered cp.async).
// Output packed fp16 hi/lo. Warps 0-3 skip the fully-masked last k-tile.
#define FROW 36
#define FVH_OFF (64*FROW*4)             /* V hi region byte offset in buffer  */
#define FBUF (128*FROW)                 /* uints per buffer (KH + VH)         */
#define FLASH_SMEM (2*FBUF*4)           /* 36864 B */

__global__ void __launch_bounds__(256) flash_tc(
    const uint32_t* __restrict__ Qh, const uint32_t* __restrict__ Ql,
    const uint32_t* __restrict__ Kh,
    const uint32_t* __restrict__ Vh,
    uint32_t* __restrict__ Oh, uint32_t* __restrict__ Ol)
{
    extern __shared__ uint32_t sm[];
    int tid = threadIdx.x, lane = tid & 31, wid = tid >> 5;
    int qblk = gridDim.x - 1 - blockIdx.x;          // heavy blocks first
    int q0 = qblk * 128;
    int bh = blockIdx.y;
    size_t base = (size_t)bh * SEQ * (HD/2);

    uint32_t smb = (uint32_t)__cvta_generic_to_shared(sm);

    // ---- stage Q (hi into buf0 area, lo into buf1 area), extract fragments ----
    {
        int r = tid >> 1, hs = (tid & 1) * 16;
        const uint4* gh = (const uint4*)(Qh + base + (size_t)(q0 + r)*(HD/2) + hs);
        const uint4* gl = (const uint4*)(Ql + base + (size_t)(q0 + r)*(HD/2) + hs);
        uint4* dh = (uint4*)(sm + r*FROW + hs);
        uint4* dl = (uint4*)(sm + FBUF + r*FROW + hs);
        dh[0]=gh[0]; dh[1]=gh[1]; dh[2]=gh[2]; dh[3]=gh[3];
        dl[0]=gl[0]; dl[1]=gl[1]; dl[2]=gl[2]; dl[3]=gl[3];
    }
    __syncthreads();

    uint32_t qh[4][4], ql[4][4];
    {
        uint32_t qa = smb + (uint32_t)(((wid*16 + (lane & 15))*FROW)*4 + (lane >> 4)*16);
        #pragma unroll
        for (int t = 0; t < 4; t++){
            ldsm_x4(qh[t], qa + t*32);
            ldsm_x4(ql[t], qa + FBUF*4 + t*32);
        }
    }
    __syncthreads();   // Q staging fully read; buffers free for cp.async

    // K/V loader assignment (hi only)
    int lr = tid >> 2;
    int lc = (tid & 3) * 8;
    uint32_t so = (uint32_t)((lr*FROW + lc)*4);

    auto kv_issue = [&](int t){
        uint32_t bb = smb + (uint32_t)((t & 1) * FBUF * 4);
        size_t gi = base + (size_t)(t*64 + lr)*(HD/2) + lc;
        cpasync16(bb + so,                Kh + gi);
        cpasync16(bb + so + 16,           Kh + gi + 4);
        cpasync16(bb + FVH_OFF + so,      Vh + gi);
        cpasync16(bb + FVH_OFF + so + 16, Vh + gi + 4);
        asm volatile("cp.async.commit_group;");
    };

    float o[8][4] = {};
    float mr0 = -INFINITY, mr1 = -INFINITY, l0 = 0.f, l1 = 0.f;
    const float scale = 0.125f;
    int r0g = q0 + wid*16 + (lane >> 2);
    int r1g = r0g + 8;

    int ktiles = 2*qblk + 2;
    kv_issue(0);
    for (int t = 0; t < ktiles; t++){
        int k0 = t * 64;
        if (t + 1 < ktiles){
            kv_issue(t + 1);
            asm volatile("cp.async.wait_group 1;");
        } else {
            asm volatile("cp.async.wait_group 0;");
        }
        __syncthreads();
        uint32_t bufo = (uint32_t)((t & 1) * FBUF * 4);

        // Last k-tile is entirely above the diagonal for warps 0-3 — skip.
        if (!(t == ktiles - 1 && wid < 4)){

        // ---- S = Q K^T (fp16x2: qh·kh + ql·kh) ----
        float s[8][4] = {};
        #pragma unroll
        for (int t4 = 0; t4 < 4; t4++){
            #pragma unroll
            for (int nb = 0; nb < 4; nb++){
                uint32_t ba = smb + bufo
                            + (uint32_t)(((nb*16 + (lane & 15))*FROW)*4 + (lane >> 4)*16 + t4*32);
                uint32_t kh4[4];
                ldsm_x4(kh4, ba);
                mma_h(s[2*nb],   qh[t4], kh4[0], kh4[2]);
                mma_h(s[2*nb+1], qh[t4], kh4[1], kh4[3]);
                mma_h(s[2*nb],   ql[t4], kh4[0], kh4[2]);
                mma_h(s[2*nb+1], ql[t4], kh4[1], kh4[3]);
            }
        }

        // ---- scale + causal mask ----
        bool need_mask = (t == ktiles - 1) || (t == ktiles - 2 && wid < 4);
        #pragma unroll
        for (int f = 0; f < 8; f++){
            int colb = k0 + (f>>1)*16 + (f&1)*8 + (lane & 3)*2;
            #pragma unroll
            for (int c = 0; c < 4; c++){
                float v = s[f][c] * scale;
                if (need_mask){
                    int kg = colb + (c & 1);
                    int qg = (c < 2) ? r0g : r1g;
                    if (kg > qg) v = -1e30f;
                }
                s[f][c] = v;
            }
        }

        // ---- online softmax ----
        float mx0 = -INFINITY, mx1 = -INFINITY;
        #pragma unroll
        for (int f = 0; f < 8; f++){
            mx0 = fmaxf(mx0, fmaxf(s[f][0], s[f][1]));
            mx1 = fmaxf(mx1, fmaxf(s[f][2], s[f][3]));
        }
        mx0 = fmaxf(mx0, __shfl_xor_sync(0xffffffffu, mx0, 1));
        mx0 = fmaxf(mx0, __shfl_xor_sync(0xffffffffu, mx0, 2));
        mx1 = fmaxf(mx1, __shfl_xor_sync(0xffffffffu, mx1, 1));
        mx1 = fmaxf(mx1, __shfl_xor_sync(0xffffffffu, mx1, 2));
        float mn0 = fmaxf(mr0, mx0), mn1 = fmaxf(mr1, mx1);
        float a0 = __expf(mr0 - mn0), a1 = __expf(mr1 - mn1);
        mr0 = mn0; mr1 = mn1;
        float ps0 = 0.f, ps1 = 0.f;
        #pragma unroll
        for (int f = 0; f < 8; f++){
            s[f][0] = __expf(s[f][0] - mn0);
            s[f][1] = __expf(s[f][1] - mn0);
            s[f][2] = __expf(s[f][2] - mn1);
            s[f][3] = __expf(s[f][3] - mn1);
            ps0 += s[f][0] + s[f][1];
            ps1 += s[f][2] + s[f][3];
        }
        ps0 += __shfl_xor_sync(0xffffffffu, ps0, 1);
        ps0 += __shfl_xor_sync(0xffffffffu, ps0, 2);
        ps1 += __shfl_xor_sync(0xffffffffu, ps1, 1);
        ps1 += __shfl_xor_sync(0xffffffffu, ps1, 2);
        l0 = l0 * a0 + ps0;
        l1 = l1 * a1 + ps1;
        #pragma unroll
        for (int f = 0; f < 8; f++){
            o[f][0] *= a0; o[f][1] *= a0;
            o[f][2] *= a1; o[f][3] *= a1;
        }

        // ---- P fragments (fp16 split in registers; exact to u^2) ----
        uint32_t ph[4][4], pl[4][4];
        #pragma unroll
        for (int t4 = 0; t4 < 4; t4++){
            split2(s[2*t4][0],   s[2*t4][1],   ph[t4][0], pl[t4][0]);
            split2(s[2*t4][2],   s[2*t4][3],   ph[t4][1], pl[t4][1]);
            split2(s[2*t4+1][0], s[2*t4+1][1], ph[t4][2], pl[t4][2]);
            split2(s[2*t4+1][2], s[2*t4+1][3], ph[t4][3], pl[t4][3]);
        }

        // ---- O += P V (fp16x2: ph·vh + pl·vh) ----
        #pragma unroll
        for (int t4 = 0; t4 < 4; t4++){
            #pragma unroll
            for (int nb = 0; nb < 4; nb++){
                uint32_t va = smb + bufo + FVH_OFF
                            + (uint32_t)(((t4*16 + (lane & 15))*FROW)*4 + (lane >> 4)*16 + nb*32);
                uint32_t vh4[4];
                ldsm_x4t(vh4, va);
                mma_h(o[2*nb],   ph[t4], vh4[0], vh4[1]);
                mma_h(o[2*nb+1], ph[t4], vh4[2], vh4[3]);
                mma_h(o[2*nb],   pl[t4], vh4[0], vh4[1]);
                mma_h(o[2*nb+1], pl[t4], vh4[2], vh4[3]);
            }
        }

        }  // end warp-skip

        __syncthreads();   // reads of this buffer done before t+2 overwrites it
    }

    // epilogue: normalize, split, write packed attn [B,S,D/2]
    int b = bh >> 3, h = bh & 7;
    float inv0 = 1.0f / l0, inv1 = 1.0f / l1;
    #pragma unroll
    for (int f = 0; f < 8; f++){
        int col = h*HD + (f>>1)*16 + (f&1)*8 + (lane & 3)*2;
        uint32_t h0,l0u,h1,l1u;
        split2(o[f][0]*inv0, o[f][1]*inv0, h0, l0u);
        split2(o[f][2]*inv1, o[f][3]*inv1, h1, l1u);
        size_t i0 = (size_t)(b*SEQ + r0g)*KP + (col>>1);
        size_t i1 = (size_t)(b*SEQ + r1g)*KP + (col>>1);
        Oh[i0] = h0;  Ol[i0] = l0u;
        Oh[i1] = h1;  Ol[i1] = l1u;
    }
}

// ---------------- launch ------------------------------------------------------
extern "C" void kernel_launch(void* const* d_in, const int* in_sizes, int n_in,
                              void* d_out, int out_size) {
    const float* x   = (const float*)d_in[0];
    const float* Wq  = (const float*)d_in[1];
    const float* Wk  = (const float*)d_in[2];
    const float* Wv  = (const float*)d_in[3];
    const float* R   = (const float*)d_in[4];
    const float* ipw = (const float*)d_in[5];
    const float* ipb = (const float*)d_in[6];
    const float* ow  = (const float*)d_in[7];
    const float* ob  = (const float*)d_in[8];
    float* out = (float*)d_out;

    uint32_t *xh,*xl,*wh,*qh,*ql,*hh,*hl,*ah,*al;
    float* tab;
    cudaGetSymbolAddress((void**)&xh, g_xh);  cudaGetSymbolAddress((void**)&xl, g_xl);
    cudaGetSymbolAddress((void**)&wh, g_wh);
    cudaGetSymbolAddress((void**)&qh, g_qh);  cudaGetSymbolAddress((void**)&ql, g_ql);
    cudaGetSymbolAddress((void**)&hh, g_hh);  cudaGetSymbolAddress((void**)&hl, g_hl);
    cudaGetSymbolAddress((void**)&ah, g_ah);  cudaGetSymbolAddress((void**)&al, g_al);
    cudaGetSymbolAddress((void**)&tab, g_tab);

    static int inited = 0;
    if (!inited) {
        cudaFuncSetAttribute(gemm_pk<0>, cudaFuncAttributeMaxDynamicSharedMemorySize, GEMM_SMEM);
        cudaFuncSetAttribute(gemm_pk<1>, cudaFuncAttributeMaxDynamicSharedMemorySize, GEMM_SMEM);
        cudaFuncSetAttribute(gemm_pk<2>, cudaFuncAttributeMaxDynamicSharedMemorySize, GEMM_SMEM);
        cudaFuncSetAttribute(flash_tc,   cudaFuncAttributeMaxDynamicSharedMemorySize, FLASH_SMEM);
        inited = 1;
    }

    const long MKP = (long)MTOT * KP;

    // 0) cos/sin table + splits
    rope_table_kernel<<<SEQ, 256>>>(R, tab);
    split_kernel<<<(MTOT*KP)/256, 256>>>((const float2*)x, xh, xl, MTOT*KP);
    split_w_kernel<<<dim3(512, 5), 256>>>((const float2*)Wq, (const float2*)Wk,
                                          (const float2*)Wv, (const float2*)ipw,
                                          (const float2*)ow, wh);

    // 1) q,k,v = x @ W^T with fused RoPE, packed out (z-batched over 3 weights)
    dim3 gq(D_MODEL/128, MTOT/128, 3);
    gemm_pk<2><<<gq, 256, GEMM_SMEM>>>(xh, xl, 0, wh, WWU,
                                       nullptr, 0, nullptr, qh, ql, MKP, tab);

    // 2) in_proj: bias + head-permute + packed out (z-batched)
    dim3 gi(D_MODEL/128, MTOT/128, 3);
    gemm_pk<1><<<gi, 256, GEMM_SMEM>>>(qh, ql, MKP, wh + 3*WWU, WWU,
                                       ipb, D_MODEL, nullptr, hh, hl, MKP, nullptr);

    // 3) causal flash attention -> packed attn (K,V hi-only)
    flash_tc<<<dim3(SEQ/128, BHX), 256, FLASH_SMEM>>>(
        hh, hl, hh + MKP, hh + 2*MKP, ah, al);

    // 4) output projection (fp32 out)
    dim3 go(D_MODEL/128, MTOT/128, 1);
    gemm_pk<0><<<go, 256, GEMM_SMEM>>>(ah, al, 0, wh + 6*WWU, 0,
                                       ob, 0, out, nullptr, nullptr, 0, nullptr);
}

// round 17
// speedup vs baseline: 1.5248x; 1.0892x over previous
#include <cuda_runtime.h>
#include <cuda_fp16.h>
#include <math.h>
#include <stdint.h>

#define D_MODEL 512
#define HEADS   8
#define HD      64
#define SEQ     2048
#define BATCH   4
#define MTOT    (BATCH*SEQ)   /* 8192 */
#define KDIM    512
#define KP      256           /* K in f16x2 uints */
#define BHX     (BATCH*HEADS)
#define WWU     (D_MODEL*KP)  /* uints per 512x512 weight */

// ---------------- scratch (packed fp16 hi/lo) ---------------------------------
__device__ __align__(16) uint32_t g_xh[MTOT*KP],    g_xl[MTOT*KP];
__device__ __align__(16) uint32_t g_wh[7*WWU];                     // weights: hi only
__device__ __align__(16) uint32_t g_qh[3*MTOT*KP],  g_ql[3*MTOT*KP];  // rotated q,k,v
__device__ __align__(16) uint32_t g_hh[3*MTOT*KP],  g_hl[3*MTOT*KP];  // heads [BH][S][HD/2]
__device__ __align__(16) uint32_t g_ah[MTOT*KP],    g_al[MTOT*KP];    // attn out packed
__device__ float g_tab[SEQ*D_MODEL];                                   // cos/sin

// ---------------- helpers ------------------------------------------------------
__device__ __forceinline__ void split2(float x, float y, uint32_t& h, uint32_t& l){
    __half2 hh = __floats2half2_rn(x, y);
    h = *(uint32_t*)&hh;
    float hx = __low2float(hh), hy = __high2float(hh);
    __half2 ll = __floats2half2_rn(x - hx, y - hy);
    l = *(uint32_t*)&ll;
}
__device__ __forceinline__ uint32_t round_h2(float x, float y){
    __half2 hh = __floats2half2_rn(x, y);
    return *(uint32_t*)&hh;
}
__device__ __forceinline__ void ldsm_x4(uint32_t* r, uint32_t addr){
    asm volatile("ldmatrix.sync.aligned.m8n8.x4.shared.b16 {%0,%1,%2,%3}, [%4];"
        : "=r"(r[0]),"=r"(r[1]),"=r"(r[2]),"=r"(r[3]) : "r"(addr));
}
__device__ __forceinline__ void ldsm_x4t(uint32_t* r, uint32_t addr){
    asm volatile("ldmatrix.sync.aligned.m8n8.x4.trans.shared.b16 {%0,%1,%2,%3}, [%4];"
        : "=r"(r[0]),"=r"(r[1]),"=r"(r[2]),"=r"(r[3]) : "r"(addr));
}
__device__ __forceinline__ void mma_h(float* c, const uint32_t* a, uint32_t b0, uint32_t b1){
    asm volatile("mma.sync.aligned.m16n8k16.row.col.f32.f16.f16.f32 "
        "{%0,%1,%2,%3},{%4,%5,%6,%7},{%8,%9},{%0,%1,%2,%3};"
        : "+f"(c[0]),"+f"(c[1]),"+f"(c[2]),"+f"(c[3])
        : "r"(a[0]),"r"(a[1]),"r"(a[2]),"r"(a[3]),"r"(b0),"r"(b1));
}
__device__ __forceinline__ void cpasync16(uint32_t saddr, const void* g){
    asm volatile("cp.async.cg.shared.global [%0], [%1], 16;" :: "r"(saddr), "l"(g));
}

// ---------------- fused split: x (hi+lo) + 5 weight groups (hi only) -----------
__global__ void split_all_kernel(
    const float2* __restrict__ x,
    const float2* __restrict__ w0, const float2* __restrict__ w1,
    const float2* __restrict__ w2, const float2* __restrict__ w3,
    const float2* __restrict__ w4,
    uint32_t* __restrict__ xh, uint32_t* __restrict__ xl,
    uint32_t* __restrict__ wh)
{
    int j = blockIdx.y;
    if (j == 0){
        // x: hi + lo split
        for (int i = blockIdx.x*256 + threadIdx.x; i < MTOT*KP; i += gridDim.x*256){
            float2 v = x[i];
            uint32_t hh, ll;
            split2(v.x, v.y, hh, ll);
            xh[i] = hh; xl[i] = ll;
        }
    } else {
        const float2* src;
        uint32_t off; int n2;
        if      (j == 1){ src = w0; off = 0;     n2 = WWU;   }
        else if (j == 2){ src = w1; off = WWU;   n2 = WWU;   }
        else if (j == 3){ src = w2; off = 2*WWU; n2 = WWU;   }
        else if (j == 4){ src = w3; off = 3*WWU; n2 = 3*WWU; }
        else            { src = w4; off = 6*WWU; n2 = WWU;   }
        for (int i = blockIdx.x*256 + threadIdx.x; i < n2; i += gridDim.x*256){
            float2 v = src[i];
            wh[off + i] = round_h2(v.x, v.y);
        }
    }
}

// ---------------- RoPE table ---------------------------------------------------
__global__ void rope_table_kernel(const float* __restrict__ R, float* __restrict__ tab){
    int i = threadIdx.x;
    int m = blockIdx.x;
    const float* Rm = R + (size_t)m * D_MODEL * D_MODEL;
    float c = Rm[(size_t)(2*i)   * D_MODEL + 2*i];
    float s = Rm[(size_t)(2*i+1) * D_MODEL + 2*i];
    ((float2*)tab)[m*(D_MODEL/2) + i] = make_float2(c, s);
}

// ---------------- fp16x2 GEMM: C = (Ah+Al) @ Bh^T ------------------------------
// Tile 128x128, BK=16, 4-buffer cp.async ring, 8 warps (4m x 2n).
// Regions per buffer: AH, AL (128 rows), BH (128 rows); row pad 12 uints (48B).
// MODE 0: +bias fp32 out  MODE 1: +bias head-permute packed  MODE 2: RoPE packed
#define RB    1536                      /* region stride, uints (128 x 12)    */
#define OF_AL RB
#define OF_BH (2*RB)
#define BUF4  (3*RB)                    /* 4608 uints = 18432 B per buffer    */
#define GEMM_SMEM (4*BUF4*4)            /* 73728 B */

template<int MODE>
__global__ void __launch_bounds__(256, 2) gemm_pk(
    const uint32_t* __restrict__ Ah, const uint32_t* __restrict__ Al, long sA,
    const uint32_t* __restrict__ Bh, long sB,
    const float* __restrict__ bias, long sBias,
    float* __restrict__ Cf, uint32_t* __restrict__ Ch, uint32_t* __restrict__ Cl,
    long sC, const float* __restrict__ tab)
{
    extern __shared__ uint32_t smu[];
    int z = blockIdx.z;
    Ah += (size_t)z * sA;  Al += (size_t)z * sA;
    Bh += (size_t)z * sB;
    if (bias) bias += (size_t)z * sBias;

    int tid  = threadIdx.x;
    int lane = tid & 31, wid = tid >> 5;
    int warp_m = wid >> 1, warp_n = wid & 1;
    int m0 = blockIdx.y * 128, n0 = blockIdx.x * 128;

    uint32_t smb = (uint32_t)__cvta_generic_to_shared(smu);

    int row = tid >> 1, hf = (tid & 1) * 4;
    const uint32_t* gAh = Ah + (size_t)(m0 + row)*KP + hf;
    const uint32_t* gAl = Al + (size_t)(m0 + row)*KP + hf;
    const uint32_t* gBh = Bh + (size_t)(n0 + row)*KP + hf;
    uint32_t sa = smb + (row*12 + hf)*4;

    const int NS = KDIM / 16;   // 32 stages
    auto issue = [&](int s){
        if (s < NS){
            uint32_t bo = (uint32_t)((s & 3) * BUF4 * 4);
            int go = s * 8;
            cpasync16(bo + sa,            gAh + go);
            cpasync16(bo + sa + OF_AL*4,  gAl + go);
            cpasync16(bo + sa + OF_BH*4,  gBh + go);
        }
        asm volatile("cp.async.commit_group;");
    };

    float acc[2][8][4] = {};
    uint32_t a_base = (uint32_t)((warp_m*32 + (lane & 15)) * 48 + (lane >> 4) * 16);
    uint32_t b_base = (uint32_t)((warp_n*64 + (lane & 15)) * 48 + (lane >> 4) * 16);

    issue(0); issue(1); issue(2);
    for (int s = 0; s < NS; s++){
        asm volatile("cp.async.wait_group 2;");
        __syncthreads();
        issue(s + 3);
        uint32_t bb = smb + (uint32_t)((s & 3) * BUF4 * 4);

        uint32_t AHf[2][4], ALf[2][4];
        #pragma unroll
        for (int mi = 0; mi < 2; mi++){
            uint32_t aa = bb + a_base + mi*16*48;
            ldsm_x4(AHf[mi], aa);
            ldsm_x4(ALf[mi], aa + OF_AL*4);
        }
        #pragma unroll
        for (int nb = 0; nb < 4; nb++){
            uint32_t BHf[4];
            ldsm_x4(BHf, bb + OF_BH*4 + b_base + nb*16*48);
            #pragma unroll
            for (int mi = 0; mi < 2; mi++){
                mma_h(acc[mi][2*nb],   AHf[mi], BHf[0], BHf[2]);
                mma_h(acc[mi][2*nb+1], AHf[mi], BHf[1], BHf[3]);
                mma_h(acc[mi][2*nb],   ALf[mi], BHf[0], BHf[2]);
                mma_h(acc[mi][2*nb+1], ALf[mi], BHf[1], BHf[3]);
            }
        }
    }

    // ---------------- epilogue ----------------
    const float2* tab2 = (const float2*)tab;
    #pragma unroll
    for (int mi = 0; mi < 2; mi++){
        #pragma unroll
        for (int ni = 0; ni < 8; ni++){
            int m = m0 + warp_m*32 + mi*16 + (lane >> 2);
            int n = n0 + warp_n*64 + ni*8 + (lane & 3)*2;
            float v0 = acc[mi][ni][0], v1 = acc[mi][ni][1];   // row m
            float v2 = acc[mi][ni][2], v3 = acc[mi][ni][3];   // row m+8
            if (MODE == 2){
                float2 cs0 = tab2[(m     & (SEQ-1)) * (D_MODEL/2) + (n >> 1)];
                float2 cs1 = tab2[((m+8) & (SEQ-1)) * (D_MODEL/2) + (n >> 1)];
                float o0 =  v0*cs0.x + v1*cs0.y;
                float o1 = -v0*cs0.y + v1*cs0.x;
                float o2 =  v2*cs1.x + v3*cs1.y;
                float o3 = -v2*cs1.y + v3*cs1.x;
                v0=o0; v1=o1; v2=o2; v3=o3;
            } else {
                float b0 = bias[n], b1 = bias[n+1];
                v0 += b0; v1 += b1; v2 += b0; v3 += b1;
            }
            if (MODE == 0){
                float* C = Cf + (size_t)z * sC;
                *(float2*)&C[(size_t)m*D_MODEL + n]     = make_float2(v0, v1);
                *(float2*)&C[(size_t)(m+8)*D_MODEL + n] = make_float2(v2, v3);
            } else {
                uint32_t h0,l0,h1,l1;
                split2(v0, v1, h0, l0);
                split2(v2, v3, h1, l1);
                size_t zo = (size_t)z * sC;
                if (MODE == 1){
                    int b = m >> 11, sq = m & (SEQ-1);
                    int hh = n >> 6,  c = n & (HD-1);
                    size_t i0 = (((size_t)(b*HEADS + hh))*SEQ + sq)*(HD/2) + (c>>1);
                    Ch[zo + i0]            = h0;  Cl[zo + i0]            = l0;
                    Ch[zo + i0 + 8*(HD/2)] = h1;  Cl[zo + i0 + 8*(HD/2)] = l1;
                } else { // MODE 2
                    size_t i0 = (size_t)m*KP + (n>>1);
                    Ch[zo + i0]        = h0;  Cl[zo + i0]        = l0;
                    Ch[zo + i0 + 8*KP] = h1;  Cl[zo + i0 + 8*KP] = l1;
                }
            }
        }
    }
}

// ---------------- fp16 flash attention (causal) --------------------------------
// Q split (hi+lo) in registers; K,V hi-only in smem (double-buffered cp.async).
// S = (qh+ql)·kh (2 passes); O += round(P)·vh (1 pass).
// Output packed fp16 hi/lo. Warps 0-3 skip the fully-masked last k-tile.
#define FROW 36
#define FVH_OFF (64*FROW*4)             /* V hi region byte offset in buffer  */
#define FBUF (128*FROW)                 /* uints per buffer (KH + VH)         */
#define FLASH_SMEM (2*FBUF*4)           /* 36864 B */

__global__ void __launch_bounds__(256) flash_tc(
    const uint32_t* __restrict__ Qh, const uint32_t* __restrict__ Ql,
    const uint32_t* __restrict__ Kh,
    const uint32_t* __restrict__ Vh,
    uint32_t* __restrict__ Oh, uint32_t* __restrict__ Ol)
{
    extern __shared__ uint32_t sm[];
    int tid = threadIdx.x, lane = tid & 31, wid = tid >> 5;
    int qblk = gridDim.x - 1 - blockIdx.x;          // heavy blocks first
    int q0 = qblk * 128;
    int bh = blockIdx.y;
    size_t base = (size_t)bh * SEQ * (HD/2);

    uint32_t smb = (uint32_t)__cvta_generic_to_shared(sm);

    // ---- stage Q (hi into buf0 area, lo into buf1 area), extract fragments ----
    {
        int r = tid >> 1, hs = (tid & 1) * 16;
        const uint4* gh = (const uint4*)(Qh + base + (size_t)(q0 + r)*(HD/2) + hs);
        const uint4* gl = (const uint4*)(Ql + base + (size_t)(q0 + r)*(HD/2) + hs);
        uint4* dh = (uint4*)(sm + r*FROW + hs);
        uint4* dl = (uint4*)(sm + FBUF + r*FROW + hs);
        dh[0]=gh[0]; dh[1]=gh[1]; dh[2]=gh[2]; dh[3]=gh[3];
        dl[0]=gl[0]; dl[1]=gl[1]; dl[2]=gl[2]; dl[3]=gl[3];
    }
    __syncthreads();

    uint32_t qh[4][4], ql[4][4];
    {
        uint32_t qa = smb + (uint32_t)(((wid*16 + (lane & 15))*FROW)*4 + (lane >> 4)*16);
        #pragma unroll
        for (int t = 0; t < 4; t++){
            ldsm_x4(qh[t], qa + t*32);
            ldsm_x4(ql[t], qa + FBUF*4 + t*32);
        }
    }
    __syncthreads();   // Q staging fully read; buffers free for cp.async

    // K/V loader assignment (hi only)
    int lr = tid >> 2;
    int lc = (tid & 3) * 8;
    uint32_t so = (uint32_t)((lr*FROW + lc)*4);

    auto kv_issue = [&](int t){
        uint32_t bb = smb + (uint32_t)((t & 1) * FBUF * 4);
        size_t gi = base + (size_t)(t*64 + lr)*(HD/2) + lc;
        cpasync16(bb + so,                Kh + gi);
        cpasync16(bb + so + 16,           Kh + gi + 4);
        cpasync16(bb + FVH_OFF + so,      Vh + gi);
        cpasync16(bb + FVH_OFF + so + 16, Vh + gi + 4);
        asm volatile("cp.async.commit_group;");
    };

    float o[8][4] = {};
    float mr0 = -INFINITY, mr1 = -INFINITY, l0 = 0.f, l1 = 0.f;
    const float scale = 0.125f;
    int r0g = q0 + wid*16 + (lane >> 2);
    int r1g = r0g + 8;

    int ktiles = 2*qblk + 2;
    kv_issue(0);
    for (int t = 0; t < ktiles; t++){
        int k0 = t * 64;
        if (t + 1 < ktiles){
            kv_issue(t + 1);
            asm volatile("cp.async.wait_group 1;");
        } else {
            asm volatile("cp.async.wait_group 0;");
        }
        __syncthreads();
        uint32_t bufo = (uint32_t)((t & 1) * FBUF * 4);

        // Last k-tile is entirely above the diagonal for warps 0-3 — skip.
        if (!(t == ktiles - 1 && wid < 4)){

        // ---- S = Q K^T (fp16x2: qh·kh + ql·kh) ----
        float s[8][4] = {};
        #pragma unroll
        for (int t4 = 0; t4 < 4; t4++){
            #pragma unroll
            for (int nb = 0; nb < 4; nb++){
                uint32_t ba = smb + bufo
                            + (uint32_t)(((nb*16 + (lane & 15))*FROW)*4 + (lane >> 4)*16 + t4*32);
                uint32_t kh4[4];
                ldsm_x4(kh4, ba);
                mma_h(s[2*nb],   qh[t4], kh4[0], kh4[2]);
                mma_h(s[2*nb+1], qh[t4], kh4[1], kh4[3]);
                mma_h(s[2*nb],   ql[t4], kh4[0], kh4[2]);
                mma_h(s[2*nb+1], ql[t4], kh4[1], kh4[3]);
            }
        }

        // ---- scale + causal mask ----
        bool need_mask = (t == ktiles - 1) || (t == ktiles - 2 && wid < 4);
        #pragma unroll
        for (int f = 0; f < 8; f++){
            int colb = k0 + (f>>1)*16 + (f&1)*8 + (lane & 3)*2;
            #pragma unroll
            for (int c = 0; c < 4; c++){
                float v = s[f][c] * scale;
                if (need_mask){
                    int kg = colb + (c & 1);
                    int qg = (c < 2) ? r0g : r1g;
                    if (kg > qg) v = -1e30f;
                }
                s[f][c] = v;
            }
        }

        // ---- online softmax ----
        float mx0 = -INFINITY, mx1 = -INFINITY;
        #pragma unroll
        for (int f = 0; f < 8; f++){
            mx0 = fmaxf(mx0, fmaxf(s[f][0], s[f][1]));
            mx1 = fmaxf(mx1, fmaxf(s[f][2], s[f][3]));
        }
        mx0 = fmaxf(mx0, __shfl_xor_sync(0xffffffffu, mx0, 1));
        mx0 = fmaxf(mx0, __shfl_xor_sync(0xffffffffu, mx0, 2));
        mx1 = fmaxf(mx1, __shfl_xor_sync(0xffffffffu, mx1, 1));
        mx1 = fmaxf(mx1, __shfl_xor_sync(0xffffffffu, mx1, 2));
        float mn0 = fmaxf(mr0, mx0), mn1 = fmaxf(mr1, mx1);
        float a0 = __expf(mr0 - mn0), a1 = __expf(mr1 - mn1);
        mr0 = mn0; mr1 = mn1;
        float ps0 = 0.f, ps1 = 0.f;
        #pragma unroll
        for (int f = 0; f < 8; f++){
            s[f][0] = __expf(s[f][0] - mn0);
            s[f][1] = __expf(s[f][1] - mn0);
            s[f][2] = __expf(s[f][2] - mn1);
            s[f][3] = __expf(s[f][3] - mn1);
            ps0 += s[f][0] + s[f][1];
            ps1 += s[f][2] + s[f][3];
        }
        ps0 += __shfl_xor_sync(0xffffffffu, ps0, 1);
        ps0 += __shfl_xor_sync(0xffffffffu, ps0, 2);
        ps1 += __shfl_xor_sync(0xffffffffu, ps1, 1);
        ps1 += __shfl_xor_sync(0xffffffffu, ps1, 2);
        l0 = l0 * a0 + ps0;
        l1 = l1 * a1 + ps1;
        #pragma unroll
        for (int f = 0; f < 8; f++){
            o[f][0] *= a0; o[f][1] *= a0;
            o[f][2] *= a1; o[f][3] *= a1;
        }

        // ---- P fragments (rounded to fp16; lo term dropped — see error model) ----
        uint32_t ph[4][4];
        #pragma unroll
        for (int t4 = 0; t4 < 4; t4++){
            ph[t4][0] = round_h2(s[2*t4][0],   s[2*t4][1]);
            ph[t4][1] = round_h2(s[2*t4][2],   s[2*t4][3]);
            ph[t4][2] = round_h2(s[2*t4+1][0], s[2*t4+1][1]);
            ph[t4][3] = round_h2(s[2*t4+1][2], s[2*t4+1][3]);
        }

        // ---- O += P V (single pass: ph·vh) ----
        #pragma unroll
        for (int t4 = 0; t4 < 4; t4++){
            #pragma unroll
            for (int nb = 0; nb < 4; nb++){
                uint32_t va = smb + bufo + FVH_OFF
                            + (uint32_t)(((t4*16 + (lane & 15))*FROW)*4 + (lane >> 4)*16 + nb*32);
                uint32_t vh4[4];
                ldsm_x4t(vh4, va);
                mma_h(o[2*nb],   ph[t4], vh4[0], vh4[1]);
                mma_h(o[2*nb+1], ph[t4], vh4[2], vh4[3]);
            }
        }

        }  // end warp-skip

        __syncthreads();   // reads of this buffer done before t+2 overwrites it
    }

    // epilogue: normalize, split, write packed attn [B,S,D/2]
    int b = bh >> 3, h = bh & 7;
    float inv0 = 1.0f / l0, inv1 = 1.0f / l1;
    #pragma unroll
    for (int f = 0; f < 8; f++){
        int col = h*HD + (f>>1)*16 + (f&1)*8 + (lane & 3)*2;
        uint32_t h0,l0u,h1,l1u;
        split2(o[f][0]*inv0, o[f][1]*inv0, h0, l0u);
        split2(o[f][2]*inv1, o[f][3]*inv1, h1, l1u);
        size_t i0 = (size_t)(b*SEQ + r0g)*KP + (col>>1);
        size_t i1 = (size_t)(b*SEQ + r1g)*KP + (col>>1);
        Oh[i0] = h0;  Ol[i0] = l0u;
        Oh[i1] = h1;  Ol[i1] = l1u;
    }
}

// ---------------- launch ------------------------------------------------------
extern "C" void kernel_launch(void* const* d_in, const int* in_sizes, int n_in,
                              void* d_out, int out_size) {
    const float* x   = (const float*)d_in[0];
    const float* Wq  = (const float*)d_in[1];
    const float* Wk  = (const float*)d_in[2];
    const float* Wv  = (const float*)d_in[3];
    const float* R   = (const float*)d_in[4];
    const float* ipw = (const float*)d_in[5];
    const float* ipb = (const float*)d_in[6];
    const float* ow  = (const float*)d_in[7];
    const float* ob  = (const float*)d_in[8];
    float* out = (float*)d_out;

    uint32_t *xh,*xl,*wh,*qh,*ql,*hh,*hl,*ah,*al;
    float* tab;
    cudaGetSymbolAddress((void**)&xh, g_xh);  cudaGetSymbolAddress((void**)&xl, g_xl);
    cudaGetSymbolAddress((void**)&wh, g_wh);
    cudaGetSymbolAddress((void**)&qh, g_qh);  cudaGetSymbolAddress((void**)&ql, g_ql);
    cudaGetSymbolAddress((void**)&hh, g_hh);  cudaGetSymbolAddress((void**)&hl, g_hl);
    cudaGetSymbolAddress((void**)&ah, g_ah);  cudaGetSymbolAddress((void**)&al, g_al);
    cudaGetSymbolAddress((void**)&tab, g_tab);

    static int inited = 0;
    if (!inited) {
        cudaFuncSetAttribute(gemm_pk<0>, cudaFuncAttributeMaxDynamicSharedMemorySize, GEMM_SMEM);
        cudaFuncSetAttribute(gemm_pk<1>, cudaFuncAttributeMaxDynamicSharedMemorySize, GEMM_SMEM);
        cudaFuncSetAttribute(gemm_pk<2>, cudaFuncAttributeMaxDynamicSharedMemorySize, GEMM_SMEM);
        cudaFuncSetAttribute(flash_tc,   cudaFuncAttributeMaxDynamicSharedMemorySize, FLASH_SMEM);
        inited = 1;
    }

    const long MKP = (long)MTOT * KP;

    // 0) cos/sin table + fused splits (one launch)
    rope_table_kernel<<<SEQ, 256>>>(R, tab);
    split_all_kernel<<<dim3(512, 6), 256>>>((const float2*)x,
                                            (const float2*)Wq, (const float2*)Wk,
                                            (const float2*)Wv, (const float2*)ipw,
                                            (const float2*)ow, xh, xl, wh);

    // 1) q,k,v = x @ W^T with fused RoPE, packed out (z-batched over 3 weights)
    dim3 gq(D_MODEL/128, MTOT/128, 3);
    gemm_pk<2><<<gq, 256, GEMM_SMEM>>>(xh, xl, 0, wh, WWU,
                                       nullptr, 0, nullptr, qh, ql, MKP, tab);

    // 2) in_proj: bias + head-permute + packed out (z-batched)
    dim3 gi(D_MODEL/128, MTOT/128, 3);
    gemm_pk<1><<<gi, 256, GEMM_SMEM>>>(qh, ql, MKP, wh + 3*WWU, WWU,
                                       ipb, D_MODEL, nullptr, hh, hl, MKP, nullptr);

    // 3) causal flash attention -> packed attn (K,V hi-only; single-pass PV)
    flash_tc<<<dim3(SEQ/128, BHX), 256, FLASH_SMEM>>>(
        hh, hl, hh + MKP, hh + 2*MKP, ah, al);

    // 4) output projection (fp32 out)
    dim3 go(D_MODEL/128, MTOT/128, 1);
    gemm_pk<0><<<go, 256, GEMM_SMEM>>>(ah, al, 0, wh + 6*WWU, 0,
                                       ob, 0, out, nullptr, nullptr, 0, nullptr);
}